// round 13
// baseline (speedup 1.0000x reference)
#include <cuda_runtime.h>
#include <cuda_fp16.h>

// 2-layer LSTM (B=2048, T=512, I=1, H=50) + FC(50->1), fp16 tensor-core v7.
// 128 persistent CTAs x 16 batch, 832 threads = TWO groups of 13 warps,
// each group: 8 batches, own B buffers, own named barrier (free-running
// phase overlap). SHUFFLE-GATE row permutation: within each 16-row M-tile,
//   rows 0..3 = gate i (kloc 0..3), rows 4..7 = gate f,
//   rows 8..11 = gate g,            rows 12..15 = gate o.
// => thread (g,tq) holds (i,g) [g<4] or (f,o) [g>=4] of hidden kloc=g&3 for
// batches 2tq,2tq+1; TWO shfl.xor(16) build a full (i,f,g,o) quad per
// thread. No scratch SMEM, no STS/LDS round-trip, no syncwarp.
//   L1: A1[208x64]  (W_hh0 | wi0 | bias1 | 0),            kt 0..3
//   L2: A2[208x112] (W_ih1 | 0 | bias2 | 0 | W_hh1 | 0),  kt 0..6
// B[batch][k] f16 (stride 136): k = [h1; x(50); 1(51); pad; h2(56..105)].

#define HID   50
#define BT    16
#define SEQL  512
#define NBATCH 2048
#define NWG   13             // warps per group
#define NTH   832
#define BSTR  136            // B row stride in halves
#define BBUFH (8 * BSTR)     // 1088 halves per buffer (8 batches)
#define SXS   513

#define OFF_SX  0
#define OFF_BH  (BT * SXS)                    // 8208 floats
#define SMEM_FLOATS (OFF_BH + 4 * BBUFH / 2)  // 10384 fl = 41.5 KB

__device__ __forceinline__ float ftanh(float v) {
    float y; asm("tanh.approx.f32 %0, %1;" : "=f"(y) : "f"(v)); return y;
}
__device__ __forceinline__ float fsigm(float v) {
    return fmaf(0.5f, ftanh(0.5f * v), 0.5f);
}
__device__ __forceinline__ unsigned packh2(float lo, float hi) {
    unsigned r;
    asm("cvt.rn.f16x2.f32 %0, %1, %2;" : "=r"(r) : "f"(hi), "f"(lo));
    return r;
}
__device__ __forceinline__ void mma16(float* d, const unsigned* a,
                                      unsigned b0, unsigned b1) {
    asm("mma.sync.aligned.m16n8k16.row.col.f32.f16.f16.f32 "
        "{%0,%1,%2,%3}, {%4,%5,%6,%7}, {%8,%9}, {%0,%1,%2,%3};"
        : "+f"(d[0]), "+f"(d[1]), "+f"(d[2]), "+f"(d[3])
        : "r"(a[0]), "r"(a[1]), "r"(a[2]), "r"(a[3]), "r"(b0), "r"(b1));
}

__global__ __launch_bounds__(NTH, 1)
void lstm2_kernel(const float* __restrict__ x,
                  const float* __restrict__ W_ih0, const float* __restrict__ W_hh0,
                  const float* __restrict__ b_ih0, const float* __restrict__ b_hh0,
                  const float* __restrict__ W_ih1, const float* __restrict__ W_hh1,
                  const float* __restrict__ b_ih1, const float* __restrict__ b_hh1,
                  const float* __restrict__ fc_W, const float* __restrict__ fc_b,
                  float* __restrict__ out)
{
    extern __shared__ float smf[];
    float*  sX  = smf + OFF_SX;
    __half* BH  = (__half*)(smf + OFF_BH);   // [2 grp][2 buf][8][BSTR]

    const int tid  = threadIdx.x;
    const int w    = tid >> 5;
    const int lane = tid & 31;
    const int g    = lane >> 2;
    const int tq   = lane & 3;
    const int wg   = (w >= NWG) ? 1 : 0;     // batch group
    const int wl   = w - NWG * wg;           // warp-in-group 0..12
    const int bg   = blockIdx.x * BT;

    // ---- prologue: x tile, zero B bufs ----
    for (int i = tid; i < BT * SEQL; i += NTH) {
        int bl = i >> 9, t = i & (SEQL - 1);
        sX[bl * SXS + t] = x[(size_t)(bg + bl) * SEQL + t];
    }
    for (int i = tid; i < 4 * BBUFH / 2; i += NTH)
        ((float*)BH)[i] = 0.0f;
    __syncthreads();
    if (tid < 16) {
        const int g2 = tid >> 3, bq2 = tid & 7;
        __half* base = BH + g2 * 2 * BBUFH;
        base[bq2 * BSTR + 51]         = __float2half(1.0f);
        base[BBUFH + bq2 * BSTR + 51] = __float2half(1.0f);
        base[bq2 * BSTR + 50] = __float2half(sX[(8 * g2 + bq2) * SXS]);
    }

    // ---- weight-stationary fp16 A fragments, SHUFFLE-GATE row permutation ----
    // tile row rloc (= g + 8*rr): gate = 2*rr + (g>>2), kloc = g&3,
    // hidden kk = 4*wl + kloc, original W row = gate*50 + kk.
    unsigned A1r[4][4], A2r[7][4];
    #pragma unroll
    for (int kt = 0; kt < 7; kt++) {
        #pragma unroll
        for (int rr = 0; rr < 2; rr++) {
            #pragma unroll
            for (int cc = 0; cc < 2; cc++) {
                const int gate = 2 * rr + (g >> 2);
                const int kk   = 4 * wl + (g & 3);
                const int wrow = gate * HID + kk;
                const int c0 = kt * 16 + 2 * tq + 8 * cc;
                float v1[2] = {0.0f, 0.0f}, v2[2] = {0.0f, 0.0f};
                #pragma unroll
                for (int e = 0; e < 2; e++) {
                    const int c = c0 + e;
                    if (kk < HID) {
                        if (kt < 4) {
                            if (c < HID)      v1[e] = W_hh0[wrow * HID + c];
                            else if (c == 50) v1[e] = W_ih0[wrow];
                            else if (c == 51) v1[e] = b_ih0[wrow] + b_hh0[wrow];
                        }
                        if (c < HID)            v2[e] = W_ih1[wrow * HID + c];
                        else if (c == 51)       v2[e] = b_ih1[wrow] + b_hh1[wrow];
                        else if (c >= 56 && c < 106) v2[e] = W_hh1[wrow * HID + (c - 56)];
                    }
                }
                if (kt < 4) A1r[kt][rr + 2 * cc] = packh2(v1[0], v1[1]);
                A2r[kt][rr + 2 * cc] = packh2(v2[0], v2[1]);
            }
        }
    }

    __half* gBH = BH + wg * 2 * BBUFH;
    const bool lo  = (g < 4);
    const int  kk  = 4 * wl + (g & 3);       // hidden unit this thread gates
    const int  bsel = 2 * tq + (lo ? 0 : 1); // batch this thread gates
    float c1 = 0.0f, c2 = 0.0f;
    __syncthreads();

    // ---- main loop (per group, independent named barriers) ----
    for (int u = 0; u <= SEQL; u++) {
        const int p = u & 1, q = p ^ 1;
        const __half* bh = gBH + p * BBUFH;

        float d1[4] = {0, 0, 0, 0}, d2[4] = {0, 0, 0, 0};
        #pragma unroll
        for (int kt = 0; kt < 7; kt++) {
            const __half* rowp = bh + g * BSTR + kt * 16 + 2 * tq;
            const unsigned b0 = *(const unsigned*)(rowp);
            const unsigned b1 = *(const unsigned*)(rowp + 8);
            mma16(d2, A2r[kt], b0, b1);
            if (kt < 4) mma16(d1, A1r[kt], b0, b1);
        }

        // ---- shuffle-gate exchange: build full (i,f,g,o) quads ----
        // lo publishes batch-b1 values, hi publishes batch-b0 values.
        float e1a = __shfl_xor_sync(0xffffffffu, lo ? d1[1] : d1[0], 16);
        float e1b = __shfl_xor_sync(0xffffffffu, lo ? d1[3] : d1[2], 16);
        float e2a = __shfl_xor_sync(0xffffffffu, lo ? d2[1] : d2[0], 16);
        float e2b = __shfl_xor_sync(0xffffffffu, lo ? d2[3] : d2[2], 16);

        __half* wh = gBH + q * BBUFH;
        if (u < SEQL) {                       // layer 1, t = u
            float gi = lo ? d1[0] : e1a;
            float gf = lo ? e1a   : d1[1];
            float gG = lo ? d1[2] : e1b;
            float go = lo ? e1b   : d1[3];
            float i1 = fsigm(gi), f1 = fsigm(gf);
            float g1 = ftanh(gG), o1 = fsigm(go);
            c1 = fmaf(f1, c1, i1 * g1);
            float h = o1 * ftanh(c1);
            if (kk < HID) wh[bsel * BSTR + kk] = __float2half(h);
        }
        if (u > 0) {                          // layer 2, t = u-1
            float gi = lo ? d2[0] : e2a;
            float gf = lo ? e2a   : d2[1];
            float gG = lo ? d2[2] : e2b;
            float go = lo ? e2b   : d2[3];
            float i2 = fsigm(gi), f2 = fsigm(gf);
            float g2 = ftanh(gG), o2 = fsigm(go);
            c2 = fmaf(f2, c2, i2 * g2);
            float h = o2 * ftanh(c2);
            if (kk < HID) wh[bsel * BSTR + 56 + kk] = __float2half(h);
        }
        if (wl == 0 && lane < 8 && u + 1 < SEQL)   // x[u+1] -> col 50
            wh[lane * BSTR + 50] = __float2half(sX[(8 * wg + lane) * SXS + (u + 1)]);

        asm volatile("bar.sync %0, %1;" :: "r"(1 + wg), "n"(NWG * 32) : "memory");
    }

    // ---- FC epilogue: h2[511] in group buf 1, cols 56..105 ----
    if (wl == 0 && lane < 8) {
        const __half* hh = gBH + BBUFH + lane * BSTR + 56;
        float acc = fc_b[0];
        #pragma unroll
        for (int k2 = 0; k2 < HID; k2++)
            acc = fmaf(__half2float(hh[k2]), fc_W[k2], acc);
        out[bg + 8 * wg + lane] = acc;
    }
}

extern "C" void kernel_launch(void* const* d_in, const int* in_sizes, int n_in,
                              void* d_out, int out_size)
{
    const float* x     = (const float*)d_in[0];
    const float* W_ih0 = (const float*)d_in[1];
    const float* W_hh0 = (const float*)d_in[2];
    const float* b_ih0 = (const float*)d_in[3];
    const float* b_hh0 = (const float*)d_in[4];
    const float* W_ih1 = (const float*)d_in[5];
    const float* W_hh1 = (const float*)d_in[6];
    const float* b_ih1 = (const float*)d_in[7];
    const float* b_hh1 = (const float*)d_in[8];
    const float* fc_W  = (const float*)d_in[9];
    const float* fc_b  = (const float*)d_in[10];
    float* out = (float*)d_out;

    const int smem_bytes = SMEM_FLOATS * (int)sizeof(float);
    cudaFuncSetAttribute(lstm2_kernel, cudaFuncAttributeMaxDynamicSharedMemorySize, smem_bytes);
    lstm2_kernel<<<NBATCH / BT, NTH, smem_bytes>>>(
        x, W_ih0, W_hh0, b_ih0, b_hh0,
        W_ih1, W_hh1, b_ih1, b_hh1, fc_W, fc_b, out);
}

// round 14
// speedup vs baseline: 1.2093x; 1.2093x over previous
#include <cuda_runtime.h>
#include <cuda_fp16.h>

// 2-layer LSTM (B=2048, T=512, I=1, H=50) + FC(50->1), fp16 tensor-core v8.
// 128 persistent CTAs x 16 batch, 448 threads = TWO groups of 7 warps,
// each group: 8 batches, own B buffers, own named barrier.
// TWO-TILE GATE SPLIT: warp wl covers hidden k in [8wl, 8wl+8) with
//   tile ALPHA rows: 0..7 = gate i (k=8wl+row), 8..15 = gate g
//   tile BETA  rows: 0..7 = gate f,              8..15 = gate o
// => thread (g,tq) holds the COMPLETE (i,f,g,o) quad for hidden 8wl+g,
// batches 2tq & 2tq+1, in its own mma output regs. No scratch SMEM,
// no shfl, no selects. c-state: 2 per layer per thread.
//   L1: A1[.x64]  (W_hh0 | wi0 | bias1 | 0),            kt 0..3
//   L2: A2[.x112] (W_ih1 | 0 | bias2 | 0 | W_hh1 | 0),  kt 0..6
// B[batch][k] f16 (stride 136): k = [h1; x(50); 1(51); pad; h2(56..105)].

#define HID   50
#define BT    16
#define SEQL  512
#define NBATCH 2048
#define NWG   7              // warps per group
#define NTH   448
#define BSTR  136            // B row stride in halves
#define BBUFH (8 * BSTR)     // 1088 halves per buffer (8 batches)
#define SXS   513

#define OFF_SX  0
#define OFF_BH  (BT * SXS)                    // 8208 floats
#define SMEM_FLOATS (OFF_BH + 4 * BBUFH / 2)  // 10384 fl = 41.5 KB

__device__ __forceinline__ float ftanh(float v) {
    float y; asm("tanh.approx.f32 %0, %1;" : "=f"(y) : "f"(v)); return y;
}
__device__ __forceinline__ float fsigm(float v) {
    return fmaf(0.5f, ftanh(0.5f * v), 0.5f);
}
__device__ __forceinline__ unsigned packh2(float lo, float hi) {
    unsigned r;
    asm("cvt.rn.f16x2.f32 %0, %1, %2;" : "=r"(r) : "f"(hi), "f"(lo));
    return r;
}
__device__ __forceinline__ void mma16(float* d, const unsigned* a,
                                      unsigned b0, unsigned b1) {
    asm("mma.sync.aligned.m16n8k16.row.col.f32.f16.f16.f32 "
        "{%0,%1,%2,%3}, {%4,%5,%6,%7}, {%8,%9}, {%0,%1,%2,%3};"
        : "+f"(d[0]), "+f"(d[1]), "+f"(d[2]), "+f"(d[3])
        : "r"(a[0]), "r"(a[1]), "r"(a[2]), "r"(a[3]), "r"(b0), "r"(b1));
}

__global__ __launch_bounds__(NTH, 1)
void lstm2_kernel(const float* __restrict__ x,
                  const float* __restrict__ W_ih0, const float* __restrict__ W_hh0,
                  const float* __restrict__ b_ih0, const float* __restrict__ b_hh0,
                  const float* __restrict__ W_ih1, const float* __restrict__ W_hh1,
                  const float* __restrict__ b_ih1, const float* __restrict__ b_hh1,
                  const float* __restrict__ fc_W, const float* __restrict__ fc_b,
                  float* __restrict__ out)
{
    extern __shared__ float smf[];
    float*  sX  = smf + OFF_SX;
    __half* BH  = (__half*)(smf + OFF_BH);   // [2 grp][2 buf][8][BSTR]

    const int tid  = threadIdx.x;
    const int w    = tid >> 5;
    const int lane = tid & 31;
    const int g    = lane >> 2;
    const int tq   = lane & 3;
    const int wg   = (w >= NWG) ? 1 : 0;     // batch group
    const int wl   = w - NWG * wg;           // warp-in-group 0..6
    const int bg   = blockIdx.x * BT;
    const int kk   = 8 * wl + g;             // hidden unit this thread owns

    // ---- prologue: x tile, zero B bufs ----
    for (int i = tid; i < BT * SEQL; i += NTH) {
        int bl = i >> 9, t = i & (SEQL - 1);
        sX[bl * SXS + t] = x[(size_t)(bg + bl) * SEQL + t];
    }
    for (int i = tid; i < 4 * BBUFH / 2; i += NTH)
        ((float*)BH)[i] = 0.0f;
    __syncthreads();
    if (tid < 16) {
        const int g2 = tid >> 3, bq2 = tid & 7;
        __half* base = BH + g2 * 2 * BBUFH;
        base[bq2 * BSTR + 51]         = __float2half(1.0f);
        base[BBUFH + bq2 * BSTR + 51] = __float2half(1.0f);
        base[bq2 * BSTR + 50] = __float2half(sX[(8 * g2 + bq2) * SXS]);
    }

    // ---- weight-stationary fp16 A fragments, two-tile gate split ----
    // tile ALPHA: rr=0 -> gate 0 (i), rr=1 -> gate 2 (g)
    // tile BETA : rr=0 -> gate 1 (f), rr=1 -> gate 3 (o)
    // wrow = gate*50 + kk  (kk >= 50 -> zero pad)
    unsigned A1a[4][4], A1b[4][4], A2a[7][4], A2b[7][4];
    #pragma unroll
    for (int kt = 0; kt < 7; kt++) {
        #pragma unroll
        for (int rr = 0; rr < 2; rr++) {
            #pragma unroll
            for (int cc = 0; cc < 2; cc++) {
                const int c0 = kt * 16 + 2 * tq + 8 * cc;
                const int wra = (2 * rr) * HID + kk;     // i or g
                const int wrb = (2 * rr + 1) * HID + kk; // f or o
                float v1a[2] = {0, 0}, v1b[2] = {0, 0};
                float v2a[2] = {0, 0}, v2b[2] = {0, 0};
                #pragma unroll
                for (int e = 0; e < 2; e++) {
                    const int c = c0 + e;
                    if (kk < HID) {
                        if (kt < 4) {
                            if (c < HID) {
                                v1a[e] = W_hh0[wra * HID + c];
                                v1b[e] = W_hh0[wrb * HID + c];
                            } else if (c == 50) {
                                v1a[e] = W_ih0[wra];
                                v1b[e] = W_ih0[wrb];
                            } else if (c == 51) {
                                v1a[e] = b_ih0[wra] + b_hh0[wra];
                                v1b[e] = b_ih1 == 0 ? 0.0f : b_ih0[wrb] + b_hh0[wrb];
                            }
                        }
                        if (c < HID) {
                            v2a[e] = W_ih1[wra * HID + c];
                            v2b[e] = W_ih1[wrb * HID + c];
                        } else if (c == 51) {
                            v2a[e] = b_ih1[wra] + b_hh1[wra];
                            v2b[e] = b_ih1[wrb] + b_hh1[wrb];
                        } else if (c >= 56 && c < 106) {
                            v2a[e] = W_hh1[wra * HID + (c - 56)];
                            v2b[e] = W_hh1[wrb * HID + (c - 56)];
                        }
                    }
                }
                if (kt < 4) {
                    A1a[kt][rr + 2 * cc] = packh2(v1a[0], v1a[1]);
                    A1b[kt][rr + 2 * cc] = packh2(v1b[0], v1b[1]);
                }
                A2a[kt][rr + 2 * cc] = packh2(v2a[0], v2a[1]);
                A2b[kt][rr + 2 * cc] = packh2(v2b[0], v2b[1]);
            }
        }
    }

    __half* gBH = BH + wg * 2 * BBUFH;
    float c1[2] = {0, 0}, c2[2] = {0, 0};
    __syncthreads();

    // ---- main loop (per group, independent named barriers) ----
    for (int u = 0; u <= SEQL; u++) {
        const int p = u & 1, q = p ^ 1;
        const __half* bh = gBH + p * BBUFH;

        float d1a[4] = {0, 0, 0, 0}, d1b[4] = {0, 0, 0, 0};
        float d2a[4] = {0, 0, 0, 0}, d2b[4] = {0, 0, 0, 0};
        #pragma unroll
        for (int kt = 0; kt < 7; kt++) {
            const __half* rowp = bh + g * BSTR + kt * 16 + 2 * tq;
            const unsigned b0 = *(const unsigned*)(rowp);
            const unsigned b1 = *(const unsigned*)(rowp + 8);
            mma16(d2a, A2a[kt], b0, b1);
            mma16(d2b, A2b[kt], b0, b1);
            if (kt < 4) {
                mma16(d1a, A1a[kt], b0, b1);
                mma16(d1b, A1b[kt], b0, b1);
            }
        }

        // ---- gate math, fully register-resident quads ----
        // batch e: i=dXa[e], f=dXb[e], g=dXa[2+e], o=dXb[2+e]
        __half* wh = gBH + q * BBUFH;
        if (u < SEQL) {                       // layer 1, t = u
            #pragma unroll
            for (int e = 0; e < 2; e++) {
                float i1 = fsigm(d1a[e]),     f1 = fsigm(d1b[e]);
                float g1 = ftanh(d1a[2 + e]), o1 = fsigm(d1b[2 + e]);
                c1[e] = fmaf(f1, c1[e], i1 * g1);
                float h = o1 * ftanh(c1[e]);
                if (kk < HID)
                    wh[(2 * tq + e) * BSTR + kk] = __float2half(h);
            }
        }
        if (u > 0) {                          // layer 2, t = u-1
            #pragma unroll
            for (int e = 0; e < 2; e++) {
                float i2 = fsigm(d2a[e]),     f2 = fsigm(d2b[e]);
                float g2 = ftanh(d2a[2 + e]), o2 = fsigm(d2b[2 + e]);
                c2[e] = fmaf(f2, c2[e], i2 * g2);
                float h = o2 * ftanh(c2[e]);
                if (kk < HID)
                    wh[(2 * tq + e) * BSTR + 56 + kk] = __float2half(h);
            }
        }
        if (wl == 0 && lane < 8 && u + 1 < SEQL)   // x[u+1] -> col 50
            wh[lane * BSTR + 50] = __float2half(sX[(8 * wg + lane) * SXS + (u + 1)]);

        asm volatile("bar.sync %0, %1;" :: "r"(1 + wg), "n"(NWG * 32) : "memory");
    }

    // ---- FC epilogue: h2[511] in group buf 1, cols 56..105 ----
    if (wl == 0 && lane < 8) {
        const __half* hh = gBH + BBUFH + lane * BSTR + 56;
        float acc = fc_b[0];
        #pragma unroll
        for (int k2 = 0; k2 < HID; k2++)
            acc = fmaf(__half2float(hh[k2]), fc_W[k2], acc);
        out[bg + 8 * wg + lane] = acc;
    }
}

extern "C" void kernel_launch(void* const* d_in, const int* in_sizes, int n_in,
                              void* d_out, int out_size)
{
    const float* x     = (const float*)d_in[0];
    const float* W_ih0 = (const float*)d_in[1];
    const float* W_hh0 = (const float*)d_in[2];
    const float* b_ih0 = (const float*)d_in[3];
    const float* b_hh0 = (const float*)d_in[4];
    const float* W_ih1 = (const float*)d_in[5];
    const float* W_hh1 = (const float*)d_in[6];
    const float* b_ih1 = (const float*)d_in[7];
    const float* b_hh1 = (const float*)d_in[8];
    const float* fc_W  = (const float*)d_in[9];
    const float* fc_b  = (const float*)d_in[10];
    float* out = (float*)d_out;

    const int smem_bytes = SMEM_FLOATS * (int)sizeof(float);
    cudaFuncSetAttribute(lstm2_kernel, cudaFuncAttributeMaxDynamicSharedMemorySize, smem_bytes);
    lstm2_kernel<<<NBATCH / BT, NTH, smem_bytes>>>(
        x, W_ih0, W_hh0, b_ih0, b_hh0,
        W_ih1, W_hh1, b_ih1, b_hh1, fc_W, fc_b, out);
}